// round 7
// baseline (speedup 1.0000x reference)
#include <cuda_runtime.h>
#include <math.h>

#define N_PTS 32
#define D_DIM 128
#define ITERS 20
#define EPSF  1e-7f
#define CLIPF 1e-7f
#define FULL  0xffffffffu
#define RS    132            // smem row stride in floats (528B)
#define MAXG  8192

__device__ double g_acc;
__device__ float  g_G[MAXG * 1024];   // per-group 32x32 NORMALIZED Gram [g][n][m]

__global__ void finalize_kernel(float* out, float invG) {
    out[0] = (float)(g_acc * (double)invG);
}

__device__ __forceinline__ float warp_sum(float v) {
#pragma unroll
    for (int k = 16; k; k >>= 1) v += __shfl_xor_sync(FULL, v, k);
    return v;
}

// packed fp32x2 FMA (Blackwell): d += a*b elementwise on float2 packed in u64
__device__ __forceinline__ void ffma2(unsigned long long& d,
                                      unsigned long long a,
                                      unsigned long long b) {
    asm("fma.rn.f32x2 %0, %1, %2, %0;" : "+l"(d) : "l"(a), "l"(b));
}
__device__ __forceinline__ float hadd2(unsigned long long v) {
    float lo, hi;
    asm("mov.b64 {%0,%1}, %2;" : "=f"(lo), "=f"(hi) : "l"(v));
    return lo + hi;
}

// ============ Kernel 1: Gram (2 warps/group, K split across lane pairs) =====
__global__ __launch_bounds__(64, 10) void gram_kernel(const float* __restrict__ X) {
    __shared__ float Xs[N_PTS * RS];   // 16896 B staging; reused for G (32x33)
    __shared__ float rn_sh[N_PTS];

    const int g    = blockIdx.x;
    const int tid  = threadIdx.x;
    const int w    = tid >> 5;
    const int lane = tid & 31;

    if (g == 0 && tid == 0) g_acc = 0.0;   // stream-ordered before kernel 2

    const float4* __restrict__ Xg = (const float4*)(X + (size_t)g * (N_PTS * D_DIM));

    // ---- load 32x128 into smem, swizzled: tile t of row r at (t+(r>>3))&31 ----
#pragma unroll
    for (int i = 0; i < 16; i++) {
        int row = 2 * i + w;
        float4 v = __ldg(&Xg[row * (D_DIM / 4) + lane]);
        int pt = (lane + (row >> 3)) & 31;
        *(float4*)&Xs[row * RS + 4 * pt] = v;
    }
    __syncthreads();

    // ---- job map: 20 triangle tiles x 2 K-halves = 40 jobs over 64 lanes ----
    // lane = 2*ti + h  (ti local tile, h K-half); warp w owns tiles w*10..w*10+9
    const bool active = (lane < 20);
    const int  ti = lane >> 1;
    const int  h  = lane & 1;
    const int  t  = w * 10 + ti;       // global tile id (valid if active)

    unsigned long long acc[4][8];
#pragma unroll
    for (int a = 0; a < 4; a++)
#pragma unroll
        for (int b = 0; b < 8; b++) acc[a][b] = 0ull;

    int I = 0, J = 0;
    if (active) {
        if      (t < 8)  { J = 0; I = t; }
        else if (t < 14) { J = 1; I = t - 6; }
        else if (t < 18) { J = 2; I = t - 10; }
        else             { J = 3; I = t - 12; }

        const int ih = I >> 1;
        const float* pa = &Xs[(4 * I) * RS];
        const float* pb = &Xs[(8 * J) * RS];
        const int t0 = h * 16;
#pragma unroll 4
        for (int k = 0; k < 16; k++) {
            int tt = t0 + k;
            int oa = ((tt + ih) & 31) << 2;
            int ob = ((tt + J)  & 31) << 2;

            ulonglong2 a0 = *(const ulonglong2*)(pa + 0 * RS + oa);
            ulonglong2 a1 = *(const ulonglong2*)(pa + 1 * RS + oa);
            ulonglong2 a2 = *(const ulonglong2*)(pa + 2 * RS + oa);
            ulonglong2 a3 = *(const ulonglong2*)(pa + 3 * RS + oa);
#pragma unroll
            for (int c = 0; c < 8; c++) {
                ulonglong2 b = *(const ulonglong2*)(pb + c * RS + ob);
                ffma2(acc[0][c], a0.x, b.x); ffma2(acc[0][c], a0.y, b.y);
                ffma2(acc[1][c], a1.x, b.x); ffma2(acc[1][c], a1.y, b.y);
                ffma2(acc[2][c], a2.x, b.x); ffma2(acc[2][c], a2.y, b.y);
                ffma2(acc[3][c], a3.x, b.x); ffma2(acc[3][c], a3.y, b.y);
            }
        }
    }
    __syncwarp();

    // ---- combine K-halves across lane pairs (lane ^ 1), then hold 4x8 tile ----
    float vv[4][8];
#pragma unroll
    for (int rr = 0; rr < 4; rr++)
#pragma unroll
        for (int c = 0; c < 8; c++) {
            float s = hadd2(acc[rr][c]);
            s += __shfl_xor_sync(FULL, s, 1);
            vv[rr][c] = s;
        }

    __syncthreads();                    // all Xs reads done before overwrite

    // ---- scatter tile + mirror into Gs (reuse Xs), layout G[32][33] ----
    float* Gs = Xs;
    if (active && h == 0) {
        const int r0 = 4 * I, c0 = 8 * J;
#pragma unroll
        for (int rr = 0; rr < 4; rr++)
#pragma unroll
            for (int c = 0; c < 8; c++) {
                float v = vv[rr][c];
                Gs[33 * (r0 + rr) + (c0 + c)] = v;
                Gs[33 * (c0 + c) + (r0 + rr)] = v;
            }
    }
    __syncthreads();

    // ---- rn from diagonal ----
    if (tid < N_PTS)
        rn_sh[tid] = 1.0f / fmaxf(sqrtf(Gs[34 * tid]), 1e-12f);
    __syncthreads();

    // ---- normalized, coalesced copy-out: g_G[g][r][c] = G*rn[r]*rn[c] ----
    float* __restrict__ out = g_G + (size_t)g * 1024;
#pragma unroll
    for (int k = 0; k < 16; k++) {
        int idx = k * 64 + tid;
        int r = idx >> 5, c = idx & 31;
        out[idx] = Gs[33 * r + c] * (rn_sh[r] * rn_sh[c]);
    }
}

// ================= Kernel 2: Karcher iterations in dot space ================
__global__ __launch_bounds__(256) void iter_kernel(int G) {
    const int warp = threadIdx.x >> 5;
    const int lane = threadIdx.x & 31;
    const int g    = blockIdx.x * 8 + warp;

    __shared__ float lsum[8];

    float l = 0.0f;
    if (g < G) {
        const float* __restrict__ Gp = g_G + (size_t)g * 1024;

        // gr[m] = normalized G[m][lane] (== G[lane][m] by symmetry, coalesced)
        float gr[N_PTS];
#pragma unroll
        for (int m = 0; m < N_PTS; m++) gr[m] = __ldg(Gp + m * 32 + lane);

        // dots0[n] = rowsum_n / max(sqrt(total), 1e-12)
        float rowsum = 0.0f;
#pragma unroll
        for (int m = 0; m < N_PTS; m++) rowsum += gr[m];
        float T = warp_sum(rowsum);
        float dot = rowsum / fmaxf(sqrtf(T), 1e-12f);

        const float invN = 1.0f / N_PTS;
#pragma unroll 1
        for (int it = 0; it < ITERS; it++) {
            float t  = fminf(fmaxf(dot, -1.0f + CLIPF), 1.0f - CLIPF);
            float th = acosf(t);
            float st = fmaxf(sqrtf(fmaf(-t, t, 1.0f)), EPSF);
            float c  = th / st;

            float s = warp_sum(c * dot);             // c . dots

            float gc0 = 0.f, gc1 = 0.f, gc2 = 0.f, gc3 = 0.f;
#pragma unroll
            for (int m = 0; m < N_PTS; m += 4) {
                float c0 = __shfl_sync(FULL, c, m);
                float c1 = __shfl_sync(FULL, c, m + 1);
                float c2 = __shfl_sync(FULL, c, m + 2);
                float c3 = __shfl_sync(FULL, c, m + 3);
                gc0 = fmaf(gr[m],     c0, gc0);
                gc1 = fmaf(gr[m + 1], c1, gc1);
                gc2 = fmaf(gr[m + 2], c2, gc2);
                gc3 = fmaf(gr[m + 3], c3, gc3);
            }
            float gc = (gc0 + gc1) + (gc2 + gc3);    // (G c)[lane]

            float A2  = warp_sum(c * gc);            // c^T G c
            float vn2 = fmaxf(A2 - s * s, 0.0f) * (invN * invN);
            float vn  = fmaxf(sqrtf(vn2), EPSF);

            float sn, cs;
            sincosf(vn, &sn, &cs);
            float sc = sn / vn;

            dot = fmaf(cs, dot, sc * invN * fmaf(-s, dot, gc));
        }

        float t  = fminf(fmaxf(dot, -1.0f + CLIPF), 1.0f - CLIPF);
        float th = acosf(t);
        l = warp_sum(th * th);
    }

    if (lane == 0) lsum[warp] = l;
    __syncthreads();
    if (threadIdx.x == 0) {
        float b = 0.0f;
#pragma unroll
        for (int w = 0; w < 8; w++) b += lsum[w];
        atomicAdd(&g_acc, (double)b);
    }
}

extern "C" void kernel_launch(void* const* d_in, const int* in_sizes, int n_in,
                              void* d_out, int out_size) {
    const float* X = (const float*)d_in[0];
    const int G = in_sizes[0] / (N_PTS * D_DIM);   // 8000 for (1000,8,32,128)

    gram_kernel<<<G, 64>>>(X);
    iter_kernel<<<(G + 7) / 8, 256>>>(G);
    finalize_kernel<<<1, 1>>>((float*)d_out, 1.0f / (float)G);
}

// round 8
// speedup vs baseline: 1.2884x; 1.2884x over previous
#include <cuda_runtime.h>
#include <math.h>

#define N_PTS 32
#define D_DIM 128
#define ITERS 20
#define EPSF  1e-7f
#define CLIPF 1e-7f
#define FULL  0xffffffffu
#define RS2   68             // smem row stride in floats (272B; 272%128==16)
#define MAXG  8192

__device__ double g_acc;
__device__ float  g_G[MAXG * 1024];   // per-group 32x32 NORMALIZED Gram [g][n][m]

__global__ void finalize_kernel(float* out, float invG) {
    out[0] = (float)(g_acc * (double)invG);
}

__device__ __forceinline__ float warp_sum(float v) {
#pragma unroll
    for (int k = 16; k; k >>= 1) v += __shfl_xor_sync(FULL, v, k);
    return v;
}

// packed fp32x2 FMA (Blackwell): d += a*b elementwise on float2 packed in u64
__device__ __forceinline__ void ffma2(unsigned long long& d,
                                      unsigned long long a,
                                      unsigned long long b) {
    asm("fma.rn.f32x2 %0, %1, %2, %0;" : "+l"(d) : "l"(a), "l"(b));
}
__device__ __forceinline__ float hadd2(unsigned long long v) {
    float lo, hi;
    asm("mov.b64 {%0,%1}, %2;" : "=f"(lo), "=f"(hi) : "l"(v));
    return lo + hi;
}

// ========== Kernel 1: Gram (1 warp/group, two-pass K staging) ===============
__global__ __launch_bounds__(32, 16) void gram_kernel(const float* __restrict__ X) {
    __shared__ float Xs[N_PTS * RS2];  // 8704 B staging; reused for G (32x33)
    __shared__ float rn_sh[N_PTS];

    const int g    = blockIdx.x;
    const int lane = threadIdx.x;

    if (g == 0 && lane == 0) g_acc = 0.0;   // stream-ordered before kernel 2

    const float4* __restrict__ Xg = (const float4*)(X + (size_t)g * (N_PTS * D_DIM));

    // ---- triangle tiles: 20 active lanes, tile (I,J), 4x8 outputs ----
    int I, J;
    if      (lane < 8)  { J = 0; I = lane; }
    else if (lane < 14) { J = 1; I = lane - 6; }
    else if (lane < 18) { J = 2; I = lane - 10; }
    else                { J = 3; I = lane - 12; }
    const bool active = (lane < 20);
    const int  ih = I >> 1;

    unsigned long long acc[4][8];
#pragma unroll
    for (int a = 0; a < 4; a++)
#pragma unroll
        for (int b = 0; b < 8; b++) acc[a][b] = 0ull;

    const int lrow = lane >> 4;        // staging: 16 lanes x 2 rows per iter
    const int ltile = lane & 15;

#pragma unroll 1
    for (int pass = 0; pass < 2; pass++) {
        // ---- stage 32 x 64 floats (16 x 16B tiles/row), rotation swizzle:
        //      physical tile (t + (row>>3)) & 15, row stride 272B ----
#pragma unroll
        for (int i = 0; i < 16; i++) {
            int row = 2 * i + lrow;
            float4 v = __ldg(&Xg[row * (D_DIM / 4) + pass * 16 + ltile]);
            int pt = (ltile + (row >> 3)) & 15;
            *(float4*)&Xs[row * RS2 + 4 * pt] = v;
        }
        __syncwarp();

        if (active) {
            const float* pa = &Xs[(4 * I) * RS2];
            const float* pb = &Xs[(8 * J) * RS2];
#pragma unroll 4
            for (int t = 0; t < 16; t++) {
                int oa = ((t + ih) & 15) << 2;
                int ob = ((t + J)  & 15) << 2;

                ulonglong2 a0 = *(const ulonglong2*)(pa + 0 * RS2 + oa);
                ulonglong2 a1 = *(const ulonglong2*)(pa + 1 * RS2 + oa);
                ulonglong2 a2 = *(const ulonglong2*)(pa + 2 * RS2 + oa);
                ulonglong2 a3 = *(const ulonglong2*)(pa + 3 * RS2 + oa);
#pragma unroll
                for (int c = 0; c < 8; c++) {
                    ulonglong2 b = *(const ulonglong2*)(pb + c * RS2 + ob);
                    ffma2(acc[0][c], a0.x, b.x); ffma2(acc[0][c], a0.y, b.y);
                    ffma2(acc[1][c], a1.x, b.x); ffma2(acc[1][c], a1.y, b.y);
                    ffma2(acc[2][c], a2.x, b.x); ffma2(acc[2][c], a2.y, b.y);
                    ffma2(acc[3][c], a3.x, b.x); ffma2(acc[3][c], a3.y, b.y);
                }
            }
        }
        __syncwarp();                  // pass reads done before restage
    }

    // ---- scatter tile + mirror into Gs (reuse Xs), layout G[32][33] ----
    float* Gs = Xs;
    if (active) {
#pragma unroll
        for (int rr = 0; rr < 4; rr++)
#pragma unroll
            for (int c = 0; c < 8; c++) {
                float v = hadd2(acc[rr][c]);
                int r = 4 * I + rr, cc = 8 * J + c;
                Gs[33 * r + cc] = v;
                Gs[33 * cc + r] = v;
            }
    }
    __syncwarp();

    // ---- rn from diagonal ----
    rn_sh[lane] = 1.0f / fmaxf(sqrtf(Gs[34 * lane]), 1e-12f);
    __syncwarp();

    // ---- normalized, coalesced copy-out: g_G[g][r][c] = G*rn[r]*rn[c] ----
    float* __restrict__ out = g_G + (size_t)g * 1024;
#pragma unroll
    for (int r = 0; r < N_PTS; r++)
        out[r * 32 + lane] = Gs[33 * r + lane] * (rn_sh[r] * rn_sh[lane]);
}

// ================= Kernel 2: Karcher iterations in dot space ================
__global__ __launch_bounds__(256) void iter_kernel(int G) {
    const int warp = threadIdx.x >> 5;
    const int lane = threadIdx.x & 31;
    const int g    = blockIdx.x * 8 + warp;

    __shared__ float lsum[8];

    float l = 0.0f;
    if (g < G) {
        const float* __restrict__ Gp = g_G + (size_t)g * 1024;

        // gr[m] = normalized G[m][lane] (== G[lane][m] by symmetry, coalesced)
        float gr[N_PTS];
#pragma unroll
        for (int m = 0; m < N_PTS; m++) gr[m] = __ldg(Gp + m * 32 + lane);

        // dots0[n] = rowsum_n / max(sqrt(total), 1e-12)
        float rowsum = 0.0f;
#pragma unroll
        for (int m = 0; m < N_PTS; m++) rowsum += gr[m];
        float T = warp_sum(rowsum);
        float dot = rowsum / fmaxf(sqrtf(T), 1e-12f);

        const float invN = 1.0f / N_PTS;
#pragma unroll 1
        for (int it = 0; it < ITERS; it++) {
            float t  = fminf(fmaxf(dot, -1.0f + CLIPF), 1.0f - CLIPF);
            float th = acosf(t);
            float st = fmaxf(sqrtf(fmaf(-t, t, 1.0f)), EPSF);
            float c  = th / st;

            // gc = (G c)[lane] first, so both reductions can overlap
            float gc0 = 0.f, gc1 = 0.f, gc2 = 0.f, gc3 = 0.f;
#pragma unroll
            for (int m = 0; m < N_PTS; m += 4) {
                float c0 = __shfl_sync(FULL, c, m);
                float c1 = __shfl_sync(FULL, c, m + 1);
                float c2 = __shfl_sync(FULL, c, m + 2);
                float c3 = __shfl_sync(FULL, c, m + 3);
                gc0 = fmaf(gr[m],     c0, gc0);
                gc1 = fmaf(gr[m + 1], c1, gc1);
                gc2 = fmaf(gr[m + 2], c2, gc2);
                gc3 = fmaf(gr[m + 3], c3, gc3);
            }
            float gc = (gc0 + gc1) + (gc2 + gc3);

            // interleaved dual butterfly: s = c.dots, A2 = c^T G c
            float pa = c * dot;
            float pb = c * gc;
#pragma unroll
            for (int k = 16; k; k >>= 1) {
                pa += __shfl_xor_sync(FULL, pa, k);
                pb += __shfl_xor_sync(FULL, pb, k);
            }
            float s = pa, A2 = pb;

            float vn2 = fmaxf(A2 - s * s, 0.0f) * (invN * invN);
            float vn  = fmaxf(sqrtf(vn2), EPSF);

            float sn, cs;
            sincosf(vn, &sn, &cs);
            float sc = sn / vn;

            dot = fmaf(cs, dot, sc * invN * fmaf(-s, dot, gc));
        }

        float t  = fminf(fmaxf(dot, -1.0f + CLIPF), 1.0f - CLIPF);
        float th = acosf(t);
        l = warp_sum(th * th);
    }

    if (lane == 0) lsum[warp] = l;
    __syncthreads();
    if (threadIdx.x == 0) {
        float b = 0.0f;
#pragma unroll
        for (int w = 0; w < 8; w++) b += lsum[w];
        atomicAdd(&g_acc, (double)b);
    }
}

extern "C" void kernel_launch(void* const* d_in, const int* in_sizes, int n_in,
                              void* d_out, int out_size) {
    const float* X = (const float*)d_in[0];
    const int G = in_sizes[0] / (N_PTS * D_DIM);   // 8000 for (1000,8,32,128)

    gram_kernel<<<G, 32>>>(X);
    iter_kernel<<<(G + 7) / 8, 256>>>(G);
    finalize_kernel<<<1, 1>>>((float*)d_out, 1.0f / (float)G);
}

// round 9
// speedup vs baseline: 1.3635x; 1.0583x over previous
#include <cuda_runtime.h>
#include <math.h>

#define N_PTS 32
#define D_DIM 128
#define ITERS 20
#define EPSF  1e-7f
#define CLIPF 1e-7f
#define FULL  0xffffffffu
#define RS2   68             // smem row stride in floats (272B; 272%128==16)
#define PI_F  3.14159265358979f

__device__ double g_acc;     // zero-init; finalize resets after each read

__global__ void finalize_kernel(float* out, float invG) {
    out[0] = (float)(g_acc * (double)invG);
    g_acc = 0.0;             // restore invariant for next graph replay
}

__device__ __forceinline__ float warp_sum(float v) {
#pragma unroll
    for (int k = 16; k; k >>= 1) v += __shfl_xor_sync(FULL, v, k);
    return v;
}

// packed fp32x2 FMA (Blackwell): d += a*b elementwise on float2 packed in u64
__device__ __forceinline__ void ffma2(unsigned long long& d,
                                      unsigned long long a,
                                      unsigned long long b) {
    asm("fma.rn.f32x2 %0, %1, %2, %0;" : "+l"(d) : "l"(a), "l"(b));
}
__device__ __forceinline__ float hadd2(unsigned long long v) {
    float lo, hi;
    asm("mov.b64 {%0,%1}, %2;" : "=f"(lo), "=f"(hi) : "l"(v));
    return lo + hi;
}

// acos via A&S 4.4.46: acos(u) = sqrt(1-u)*poly(u), u in [0,1], |err|<=2e-8
__device__ __forceinline__ float acos_poly(float t) {
    float u = fabsf(t);
    float p = fmaf(u, -0.0012624911f, 0.0066700901f);
    p = fmaf(u, p, -0.0170881256f);
    p = fmaf(u, p,  0.0308918810f);
    p = fmaf(u, p, -0.0501743046f);
    p = fmaf(u, p,  0.0889789874f);
    p = fmaf(u, p, -0.2145988016f);
    p = fmaf(u, p,  1.5707963050f);
    float r = sqrtf(1.0f - u) * p;
    return (t >= 0.0f) ? r : (PI_F - r);
}

// ========== Fused: Gram (1 warp/group, two-pass K) + Karcher iters ==========
__global__ __launch_bounds__(32, 16) void karcher_fused(const float* __restrict__ X) {
    __shared__ float Xs[N_PTS * RS2];  // 8704 B staging; reused for G (32x33)
    __shared__ float rn_sh[N_PTS];

    const int g    = blockIdx.x;
    const int lane = threadIdx.x;

    const float4* __restrict__ Xg = (const float4*)(X + (size_t)g * (N_PTS * D_DIM));

    // ---- triangle tiles: 20 active lanes, tile (I,J), 4x8 outputs ----
    int I, J;
    if      (lane < 8)  { J = 0; I = lane; }
    else if (lane < 14) { J = 1; I = lane - 6; }
    else if (lane < 18) { J = 2; I = lane - 10; }
    else                { J = 3; I = lane - 12; }
    const bool active = (lane < 20);
    const int  ih = I >> 1;

    unsigned long long acc[4][8];
#pragma unroll
    for (int a = 0; a < 4; a++)
#pragma unroll
        for (int b = 0; b < 8; b++) acc[a][b] = 0ull;

    const int lrow = lane >> 4;        // staging: 16 lanes x 2 rows per iter
    const int ltile = lane & 15;

#pragma unroll 1
    for (int pass = 0; pass < 2; pass++) {
        // stage 32 x 64 floats, rotation swizzle: phys tile (t+(row>>3))&15
#pragma unroll
        for (int i = 0; i < 16; i++) {
            int row = 2 * i + lrow;
            float4 v = __ldg(&Xg[row * (D_DIM / 4) + pass * 16 + ltile]);
            int pt = (ltile + (row >> 3)) & 15;
            *(float4*)&Xs[row * RS2 + 4 * pt] = v;
        }
        __syncwarp();

        if (active) {
            const float* pa = &Xs[(4 * I) * RS2];
            const float* pb = &Xs[(8 * J) * RS2];
#pragma unroll 4
            for (int t = 0; t < 16; t++) {
                int oa = ((t + ih) & 15) << 2;
                int ob = ((t + J)  & 15) << 2;

                ulonglong2 a0 = *(const ulonglong2*)(pa + 0 * RS2 + oa);
                ulonglong2 a1 = *(const ulonglong2*)(pa + 1 * RS2 + oa);
                ulonglong2 a2 = *(const ulonglong2*)(pa + 2 * RS2 + oa);
                ulonglong2 a3 = *(const ulonglong2*)(pa + 3 * RS2 + oa);
#pragma unroll
                for (int c = 0; c < 8; c++) {
                    ulonglong2 b = *(const ulonglong2*)(pb + c * RS2 + ob);
                    ffma2(acc[0][c], a0.x, b.x); ffma2(acc[0][c], a0.y, b.y);
                    ffma2(acc[1][c], a1.x, b.x); ffma2(acc[1][c], a1.y, b.y);
                    ffma2(acc[2][c], a2.x, b.x); ffma2(acc[2][c], a2.y, b.y);
                    ffma2(acc[3][c], a3.x, b.x); ffma2(acc[3][c], a3.y, b.y);
                }
            }
        }
        __syncwarp();                  // pass reads done before restage
    }

    // ---- scatter tile + mirror into Gs (reuse Xs), layout G[32][33] ----
    float* Gs = Xs;
    if (active) {
#pragma unroll
        for (int rr = 0; rr < 4; rr++)
#pragma unroll
            for (int c = 0; c < 8; c++) {
                float v = hadd2(acc[rr][c]);
                int r = 4 * I + rr, cc = 8 * J + c;
                Gs[33 * r + cc] = v;
                Gs[33 * cc + r] = v;
            }
    }
    __syncwarp();

    // ---- rn from diagonal ----
    rn_sh[lane] = rsqrtf(fmaxf(Gs[34 * lane], 1e-24f));
    __syncwarp();

    // ---- lane reads its Gram column (conflict-free), normalized ----
    float gr[N_PTS];
    {
        float rl = rn_sh[lane];
#pragma unroll
        for (int m = 0; m < N_PTS; m++)
            gr[m] = Gs[33 * m + lane] * (rn_sh[m] * rl);
    }

    // ---- init dots: dots0[n] = rowsum_n / sqrt(total) ----
    float rowsum = 0.0f;
#pragma unroll
    for (int m = 0; m < N_PTS; m++) rowsum += gr[m];
    float T = warp_sum(rowsum);
    float dot = rowsum * rsqrtf(fmaxf(T, 1e-24f));

    // ---- 20 Karcher iterations in dot space ----
    const float invN = 1.0f / N_PTS;
#pragma unroll 1
    for (int it = 0; it < ITERS; it++) {
        float t  = fminf(fmaxf(dot, -1.0f + CLIPF), 1.0f - CLIPF);
        float th = acos_poly(t);
        float st = sqrtf(fmaf(-t, t, 1.0f));   // >= 4.4e-4, clamp never binds
        float c  = __fdividef(th, st);

        // gc = (G c)[lane]
        float gc0 = 0.f, gc1 = 0.f, gc2 = 0.f, gc3 = 0.f;
#pragma unroll
        for (int m = 0; m < N_PTS; m += 4) {
            float c0 = __shfl_sync(FULL, c, m);
            float c1 = __shfl_sync(FULL, c, m + 1);
            float c2 = __shfl_sync(FULL, c, m + 2);
            float c3 = __shfl_sync(FULL, c, m + 3);
            gc0 = fmaf(gr[m],     c0, gc0);
            gc1 = fmaf(gr[m + 1], c1, gc1);
            gc2 = fmaf(gr[m + 2], c2, gc2);
            gc3 = fmaf(gr[m + 3], c3, gc3);
        }
        float gc = (gc0 + gc1) + (gc2 + gc3);

        // interleaved dual butterfly: s = c.dots, A2 = c^T G c
        float pa = c * dot;
        float pb = c * gc;
#pragma unroll
        for (int k = 16; k; k >>= 1) {
            pa += __shfl_xor_sync(FULL, pa, k);
            pb += __shfl_xor_sync(FULL, pb, k);
        }
        float s = pa, A2 = pb;

        float vn2 = fmaxf(A2 - s * s, 0.0f) * (invN * invN);
        float vn  = fmaxf(sqrtf(vn2), EPSF);

        float sc = __fdividef(__sinf(vn), vn);
        float cs = __cosf(vn);

        dot = fmaf(cs, dot, sc * invN * fmaf(-s, dot, gc));
    }

    // ---- loss_g = sum_n acos(clip(dot_n))^2 ----
    {
        float t  = fminf(fmaxf(dot, -1.0f + CLIPF), 1.0f - CLIPF);
        float th = acos_poly(t);
        float l  = warp_sum(th * th);
        if (lane == 0) atomicAdd(&g_acc, (double)l);
    }
}

extern "C" void kernel_launch(void* const* d_in, const int* in_sizes, int n_in,
                              void* d_out, int out_size) {
    const float* X = (const float*)d_in[0];
    const int G = in_sizes[0] / (N_PTS * D_DIM);   // 8000 for (1000,8,32,128)

    karcher_fused<<<G, 32>>>(X);
    finalize_kernel<<<1, 1>>>((float*)d_out, 1.0f / (float)G);
}